// round 11
// baseline (speedup 1.0000x reference)
#include <cuda_runtime.h>
#include <cuda_fp16.h>
#include <cstdint>

#define N_NODES 50000
#define D       128
#define CAP     64          // max degree capacity (mean 16, sigma 4 -> safe)
#define GEMM_ROWS 32        // rows per GEMM block
#define GB ((N_NODES + GEMM_ROWS - 1) / GEMM_ROWS)   // 1563 gemm blocks

// ---- scratch (static device globals; zero-initialized at load) ----
__device__ uint2  g_Ph[(size_t)N_NODES * 32];       // P in f16: row = 32 uint2
__device__ __half g_Wh[D * D];                      // W in f16 (same layout as W)
__device__ int    g_cursor[N_NODES];                // degree counts; re-zeroed by gather
__device__ int2   g_slots[(size_t)N_NODES * CAP];   // {src, w-bits} per edge

// ---- f32x2 packed-FMA helpers (sm_103a) ----
__device__ __forceinline__ void fma2(unsigned long long& d,
                                     unsigned long long a,
                                     unsigned long long b) {
    asm("fma.rn.f32x2 %0, %1, %2, %0;" : "+l"(d) : "l"(a), "l"(b));
}
__device__ __forceinline__ unsigned long long packdup(float x) {
    unsigned long long r;
    asm("mov.b64 %0, {%1, %1};" : "=l"(r) : "f"(x));
    return r;
}
__device__ __forceinline__ unsigned long long pack2(float2 v) {
    unsigned long long r;
    asm("mov.b64 %0, {%1, %2};" : "=l"(r) : "f"(v.x), "f"(v.y));
    return r;
}
__device__ __forceinline__ float2 unpack2(unsigned long long v) {
    float2 r;
    asm("mov.b64 {%0, %1}, %2;" : "=f"(r.x), "=f"(r.y) : "l"(v));
    return r;
}

// ===========================================================================
// K0: convert W to f16 (16384 elems; one float4 -> uint2 per thread).
// ===========================================================================
__global__ void wcvt_kernel(const float* __restrict__ W) {
    int i = blockIdx.x * blockDim.x + threadIdx.x;   // float4 index
    if (i < (D * D) / 4) {
        float4 w = __ldg(reinterpret_cast<const float4*>(W) + i);
        __half2 h0 = __float22half2_rn(make_float2(w.x, w.y));
        __half2 h1 = __float22half2_rn(make_float2(w.z, w.w));
        uint2 pk;
        pk.x = *reinterpret_cast<const unsigned int*>(&h0);
        pk.y = *reinterpret_cast<const unsigned int*>(&h1);
        reinterpret_cast<uint2*>(g_Wh)[i] = pk;
    }
}

// ===========================================================================
// K1: heterogeneous — blocks [0,GB) compute P = feat @ Wh (f16 W, f32 acc,
// f16 P out); blocks [GB, GB+FB) bucket edges into g_slots.
// W loads are 8B/lane (2 L1 wavefronts vs 4 for f32) -> lower wf floor.
// ===========================================================================
__global__ void __launch_bounds__(256)
gemm_fill_kernel(const float* __restrict__ feat,
                 const int* __restrict__ src,
                 const int* __restrict__ dst,
                 const float* __restrict__ ew,
                 int E) {
    __shared__ float sA[GEMM_ROWS][D];   // 16KB

    if (blockIdx.x >= GB) {
        // ---------------- fill part: one edge per thread ----------------
        int i = (blockIdx.x - GB) * 256 + threadIdx.x;
        if (i < E) {
            int d = __ldg(dst + i);
            int p = atomicAdd(&g_cursor[d], 1);
            if (p < CAP)
                g_slots[(size_t)d * CAP + p] =
                    make_int2(__ldg(src + i), __float_as_int(__ldg(ew + i)));
        }
        return;
    }

    // ---------------- GEMM part: 32 rows, 4 rows per warp ----------------
    const int t = threadIdx.x;
    const int block_row = blockIdx.x * GEMM_ROWS;

    #pragma unroll
    for (int it = 0; it < (GEMM_ROWS * 32) / 256; it++) {
        int i  = it * 256 + t;
        int r  = i >> 5;
        int c4 = i & 31;
        int row = block_row + r;
        float4 f = (row < N_NODES)
            ? __ldg(reinterpret_cast<const float4*>(feat + (size_t)row * D) + c4)
            : make_float4(0.f, 0.f, 0.f, 0.f);
        *reinterpret_cast<float4*>(&sA[r][c4 * 4]) = f;
    }
    __syncthreads();

    const int warp = t >> 5;
    const int lane = t & 31;
    const int r0 = warp * 4;

    unsigned long long acc[4][2];
    #pragma unroll
    for (int r = 0; r < 4; r++) { acc[r][0] = 0ull; acc[r][1] = 0ull; }

    const uint2* W2 = reinterpret_cast<const uint2*>(g_Wh);

    #pragma unroll 4
    for (int k = 0; k < D; k++) {
        uint2 wp = __ldg(W2 + k * 32 + lane);            // cols [4l, 4l+4) f16
        float2 f01 = __half22float2(*reinterpret_cast<const __half2*>(&wp.x));
        float2 f23 = __half22float2(*reinterpret_cast<const __half2*>(&wp.y));
        unsigned long long wx = pack2(f01);
        unsigned long long wy = pack2(f23);
        unsigned long long a0 = packdup(sA[r0 + 0][k]);
        unsigned long long a1 = packdup(sA[r0 + 1][k]);
        unsigned long long a2 = packdup(sA[r0 + 2][k]);
        unsigned long long a3 = packdup(sA[r0 + 3][k]);
        fma2(acc[0][0], wx, a0); fma2(acc[0][1], wy, a0);
        fma2(acc[1][0], wx, a1); fma2(acc[1][1], wy, a1);
        fma2(acc[2][0], wx, a2); fma2(acc[2][1], wy, a2);
        fma2(acc[3][0], wx, a3); fma2(acc[3][1], wy, a3);
    }

    // Epilogue: convert to f16 pairs, one uint2 store per row.
    #pragma unroll
    for (int r = 0; r < 4; r++) {
        int row = block_row + r0 + r;
        if (row < N_NODES) {
            float2 p0 = unpack2(acc[r][0]);
            float2 p1 = unpack2(acc[r][1]);
            __half2 h0 = __float22half2_rn(p0);
            __half2 h1 = __float22half2_rn(p1);
            uint2 pk;
            pk.x = *reinterpret_cast<const unsigned int*>(&h0);
            pk.y = *reinterpret_cast<const unsigned int*>(&h1);
            g_Ph[(size_t)row * 32 + lane] = pk;
        }
    }
}

// ===========================================================================
// K2: gather.  out[n] = 0.5*(P[n] + sum w*P[src]), P in f16, fp32 accum.
// One warp per node; 4-wide unroll; launch_bounds(256,8) caps regs at 32
// so occupancy reaches 100% (was 61% at 40 regs).
// ===========================================================================
__global__ void __launch_bounds__(256, 8)
gather_kernel(float* __restrict__ out) {
    int gid  = blockIdx.x * blockDim.x + threadIdx.x;
    int node = gid >> 5;
    int lane = gid & 31;
    if (node >= N_NODES) return;

    int cnt = g_cursor[node];
    if (lane == 0) g_cursor[node] = 0;   // restore invariant (off critical path)
    if (cnt > CAP) cnt = CAP;
    const int2* sl = g_slots + (size_t)node * CAP;

    int2 my = make_int2(0, 0);
    if (lane < cnt) my = __ldg(sl + lane);

    // self term
    float4 acc;
    {
        uint2 pk = g_Ph[(size_t)node * 32 + lane];
        float2 f0 = __half22float2(*reinterpret_cast<const __half2*>(&pk.x));
        float2 f1 = __half22float2(*reinterpret_cast<const __half2*>(&pk.y));
        acc = make_float4(f0.x, f0.y, f1.x, f1.y);
    }

    const int lim = (cnt < 32) ? cnt : 32;
    int i = 0;
    for (; i + 4 <= lim; i += 4) {
        int   s[4];
        float w[4];
        #pragma unroll
        for (int j = 0; j < 4; j++) {
            s[j] = __shfl_sync(0xFFFFFFFFu, my.x, i + j);
            w[j] = __int_as_float(__shfl_sync(0xFFFFFFFFu, my.y, i + j));
        }
        uint2 pv[4];
        #pragma unroll
        for (int j = 0; j < 4; j++) pv[j] = g_Ph[(size_t)s[j] * 32 + lane];
        #pragma unroll
        for (int j = 0; j < 4; j++) {
            float2 f0 = __half22float2(*reinterpret_cast<const __half2*>(&pv[j].x));
            float2 f1 = __half22float2(*reinterpret_cast<const __half2*>(&pv[j].y));
            acc.x += w[j] * f0.x;
            acc.y += w[j] * f0.y;
            acc.z += w[j] * f1.x;
            acc.w += w[j] * f1.y;
        }
    }
    for (; i < lim; i++) {
        int   s = __shfl_sync(0xFFFFFFFFu, my.x, i);
        float w = __int_as_float(__shfl_sync(0xFFFFFFFFu, my.y, i));
        uint2 pk = g_Ph[(size_t)s * 32 + lane];
        float2 f0 = __half22float2(*reinterpret_cast<const __half2*>(&pk.x));
        float2 f1 = __half22float2(*reinterpret_cast<const __half2*>(&pk.y));
        acc.x += w * f0.x; acc.y += w * f0.y;
        acc.z += w * f1.x; acc.w += w * f1.y;
    }
    for (; i < cnt; i++) {   // rare tail: degree > 32
        int2 e = __ldg(sl + i);
        float w = __int_as_float(e.y);
        uint2 pk = g_Ph[(size_t)e.x * 32 + lane];
        float2 f0 = __half22float2(*reinterpret_cast<const __half2*>(&pk.x));
        float2 f1 = __half22float2(*reinterpret_cast<const __half2*>(&pk.y));
        acc.x += w * f0.x; acc.y += w * f0.y;
        acc.z += w * f1.x; acc.w += w * f1.y;
    }

    acc.x *= 0.5f; acc.y *= 0.5f; acc.z *= 0.5f; acc.w *= 0.5f;
    reinterpret_cast<float4*>(out)[(size_t)node * 32 + lane] = acc;
}

// ===========================================================================
// Launch. Inputs: feature [N*D] f32, edge_src [E] i32, edge_dst [E] i32,
// edge_w [E] f32, weight [D*D] f32. Output: [N*D] f32.
// ===========================================================================
extern "C" void kernel_launch(void* const* d_in, const int* in_sizes, int n_in,
                              void* d_out, int out_size) {
    const float* feat = (const float*)d_in[0];
    const int*   src  = (const int*)d_in[1];
    const int*   dst  = (const int*)d_in[2];
    const float* ew   = (const float*)d_in[3];
    const float* W    = (const float*)d_in[4];
    float* out = (float*)d_out;

    const int E  = in_sizes[1];
    const int FB = (E + 255) / 256;

    wcvt_kernel<<<16, 256>>>(W);
    gemm_fill_kernel<<<GB + FB, 256>>>(feat, src, dst, ew, E);
    gather_kernel<<<(N_NODES * 32 + 255) / 256, 256>>>(out);
}

// round 12
// speedup vs baseline: 1.4814x; 1.4814x over previous
#include <cuda_runtime.h>
#include <cuda_fp16.h>
#include <cstdint>

#define N_NODES 50000
#define D       128
#define CAP     64          // max degree capacity (mean 16, sigma 4 -> safe)
#define GEMM_ROWS 64        // rows per GEMM block (8 warps x 8 rows)
#define GB ((N_NODES + GEMM_ROWS - 1) / GEMM_ROWS)   // 782 gemm blocks

// ---- scratch (static device globals; zero-initialized at load) ----
__device__ uint2 g_Ph[(size_t)N_NODES * 32];        // P in f16: row = 32 uint2
__device__ int   g_cursor[N_NODES];                 // degree counts; re-zeroed by gather
__device__ int2  g_slots[(size_t)N_NODES * CAP];    // {src, w-bits} per edge

// ---- f32x2 packed-FMA helpers (sm_103a) ----
__device__ __forceinline__ void fma2(unsigned long long& d,
                                     unsigned long long a,
                                     unsigned long long b) {
    asm("fma.rn.f32x2 %0, %1, %2, %0;" : "+l"(d) : "l"(a), "l"(b));
}
__device__ __forceinline__ unsigned long long packdup(float x) {
    unsigned long long r;
    asm("mov.b64 %0, {%1, %1};" : "=l"(r) : "f"(x));
    return r;
}
__device__ __forceinline__ float2 unpack2(unsigned long long v) {
    float2 r;
    asm("mov.b64 {%0, %1}, %2;" : "=f"(r.x), "=f"(r.y) : "l"(v));
    return r;
}

// ===========================================================================
// K1: heterogeneous — blocks [0,GB) compute P = feat @ W (f32 math, f16 P
// out); blocks [GB, GB+FB) bucket edges into g_slots.
// GEMM: 64 rows/block, 8 rows/warp — halves per-warp W streaming vs the
// 32-row tile (the L1-wavefront bottleneck). Inner loop is the proven
// R7/R10 pattern unchanged.
// ===========================================================================
__global__ void __launch_bounds__(256, 4)
gemm_fill_kernel(const float* __restrict__ feat,
                 const float* __restrict__ W,
                 const int* __restrict__ src,
                 const int* __restrict__ dst,
                 const float* __restrict__ ew,
                 int E) {
    __shared__ float sA[GEMM_ROWS][D];   // 32KB

    if (blockIdx.x >= GB) {
        // ---------------- fill part: one edge per thread ----------------
        int i = (blockIdx.x - GB) * 256 + threadIdx.x;
        if (i < E) {
            int d = __ldg(dst + i);
            int p = atomicAdd(&g_cursor[d], 1);
            if (p < CAP)
                g_slots[(size_t)d * CAP + p] =
                    make_int2(__ldg(src + i), __float_as_int(__ldg(ew + i)));
        }
        return;
    }

    // ---------------- GEMM part: 64 rows, 8 rows per warp ----------------
    const int t = threadIdx.x;
    const int block_row = blockIdx.x * GEMM_ROWS;

    #pragma unroll
    for (int it = 0; it < (GEMM_ROWS * 32) / 256; it++) {
        int i  = it * 256 + t;
        int r  = i >> 5;
        int c4 = i & 31;
        int row = block_row + r;
        float4 f = (row < N_NODES)
            ? __ldg(reinterpret_cast<const float4*>(feat + (size_t)row * D) + c4)
            : make_float4(0.f, 0.f, 0.f, 0.f);
        *reinterpret_cast<float4*>(&sA[r][c4 * 4]) = f;
    }
    __syncthreads();

    const int warp = t >> 5;
    const int lane = t & 31;
    const int r0 = warp * 8;

    unsigned long long acc[8][2];
    #pragma unroll
    for (int r = 0; r < 8; r++) { acc[r][0] = 0ull; acc[r][1] = 0ull; }

    const ulonglong2* W8 = reinterpret_cast<const ulonglong2*>(W);

    #pragma unroll 2
    for (int k = 0; k < D; k++) {
        ulonglong2 w = __ldg(W8 + k * (D / 4) + lane);
        #pragma unroll
        for (int r = 0; r < 8; r++) {
            unsigned long long a = packdup(sA[r0 + r][k]);
            fma2(acc[r][0], w.x, a);
            fma2(acc[r][1], w.y, a);
        }
    }

    // Epilogue: convert to f16 pairs, one uint2 store per row.
    #pragma unroll
    for (int r = 0; r < 8; r++) {
        int row = block_row + r0 + r;
        if (row < N_NODES) {
            float2 p0 = unpack2(acc[r][0]);
            float2 p1 = unpack2(acc[r][1]);
            __half2 h0 = __float22half2_rn(p0);
            __half2 h1 = __float22half2_rn(p1);
            uint2 pk;
            pk.x = *reinterpret_cast<const unsigned int*>(&h0);
            pk.y = *reinterpret_cast<const unsigned int*>(&h1);
            g_Ph[(size_t)row * 32 + lane] = pk;
        }
    }
}

// ===========================================================================
// K2: gather.  out[n] = 0.5*(P[n] + sum w*P[src]), P in f16, fp32 accum.
// One warp per node; 8-wide MLP; shfl-served slot entries.
// (Unchanged from the proven R10 version.)
// ===========================================================================
__global__ void __launch_bounds__(256)
gather_kernel(float* __restrict__ out) {
    int gid  = blockIdx.x * blockDim.x + threadIdx.x;
    int node = gid >> 5;
    int lane = gid & 31;
    if (node >= N_NODES) return;

    int cnt = g_cursor[node];
    if (cnt > CAP) cnt = CAP;
    const int2* sl = g_slots + (size_t)node * CAP;

    int2 my = make_int2(0, 0);
    if (lane < cnt) my = __ldg(sl + lane);

    // self term
    float4 acc;
    {
        uint2 pk = g_Ph[(size_t)node * 32 + lane];
        float2 f0 = __half22float2(*reinterpret_cast<const __half2*>(&pk.x));
        float2 f1 = __half22float2(*reinterpret_cast<const __half2*>(&pk.y));
        acc = make_float4(f0.x, f0.y, f1.x, f1.y);
    }

    const int lim = (cnt < 32) ? cnt : 32;
    int i = 0;
    for (; i + 8 <= lim; i += 8) {
        int   s[8];
        float w[8];
        #pragma unroll
        for (int j = 0; j < 8; j++) {
            s[j] = __shfl_sync(0xFFFFFFFFu, my.x, i + j);
            w[j] = __int_as_float(__shfl_sync(0xFFFFFFFFu, my.y, i + j));
        }
        uint2 pv[8];
        #pragma unroll
        for (int j = 0; j < 8; j++) pv[j] = g_Ph[(size_t)s[j] * 32 + lane];
        #pragma unroll
        for (int j = 0; j < 8; j++) {
            float2 f0 = __half22float2(*reinterpret_cast<const __half2*>(&pv[j].x));
            float2 f1 = __half22float2(*reinterpret_cast<const __half2*>(&pv[j].y));
            acc.x += w[j] * f0.x;
            acc.y += w[j] * f0.y;
            acc.z += w[j] * f1.x;
            acc.w += w[j] * f1.y;
        }
    }
    for (; i < lim; i++) {
        int   s = __shfl_sync(0xFFFFFFFFu, my.x, i);
        float w = __int_as_float(__shfl_sync(0xFFFFFFFFu, my.y, i));
        uint2 pk = g_Ph[(size_t)s * 32 + lane];
        float2 f0 = __half22float2(*reinterpret_cast<const __half2*>(&pk.x));
        float2 f1 = __half22float2(*reinterpret_cast<const __half2*>(&pk.y));
        acc.x += w * f0.x; acc.y += w * f0.y;
        acc.z += w * f1.x; acc.w += w * f1.y;
    }
    for (; i < cnt; i++) {   // rare tail: degree > 32
        int2 e = __ldg(sl + i);
        float w = __int_as_float(e.y);
        uint2 pk = g_Ph[(size_t)e.x * 32 + lane];
        float2 f0 = __half22float2(*reinterpret_cast<const __half2*>(&pk.x));
        float2 f1 = __half22float2(*reinterpret_cast<const __half2*>(&pk.y));
        acc.x += w * f0.x; acc.y += w * f0.y;
        acc.z += w * f1.x; acc.w += w * f1.y;
    }

    acc.x *= 0.5f; acc.y *= 0.5f; acc.z *= 0.5f; acc.w *= 0.5f;
    reinterpret_cast<float4*>(out)[(size_t)node * 32 + lane] = acc;

    if (lane == 0) g_cursor[node] = 0;   // restore invariant for next call
}

// ===========================================================================
// Launch. Inputs: feature [N*D] f32, edge_src [E] i32, edge_dst [E] i32,
// edge_w [E] f32, weight [D*D] f32. Output: [N*D] f32.
// ===========================================================================
extern "C" void kernel_launch(void* const* d_in, const int* in_sizes, int n_in,
                              void* d_out, int out_size) {
    const float* feat = (const float*)d_in[0];
    const int*   src  = (const int*)d_in[1];
    const int*   dst  = (const int*)d_in[2];
    const float* ew   = (const float*)d_in[3];
    const float* W    = (const float*)d_in[4];
    float* out = (float*)d_out;

    const int E  = in_sizes[1];
    const int FB = (E + 255) / 256;

    gemm_fill_kernel<<<GB + FB, 256>>>(feat, W, src, dst, ew, E);
    gather_kernel<<<(N_NODES * 32 + 255) / 256, 256>>>(out);
}

// round 13
// speedup vs baseline: 1.5142x; 1.0222x over previous
#include <cuda_runtime.h>
#include <cuda_fp16.h>
#include <cstdint>

#define N_NODES 50000
#define D       128
#define CAP     64          // max degree capacity (mean 16, sigma 4 -> safe)
#define GEMM_ROWS 64        // rows per GEMM block (8 warps x 4 row-pairs)
#define GB ((N_NODES + GEMM_ROWS - 1) / GEMM_ROWS)   // 782 gemm blocks

// ---- scratch (static device globals; zero-initialized at load) ----
__device__ uint2 g_Ph[(size_t)N_NODES * 32];        // P in f16: row = 32 uint2
__device__ int   g_cursor[N_NODES];                 // degree counts; re-zeroed by gather
__device__ int2  g_slots[(size_t)N_NODES * CAP];    // {src, w-bits} per edge

// ---- f32x2 packed-FMA helpers (sm_103a) ----
__device__ __forceinline__ void fma2(unsigned long long& d,
                                     unsigned long long a,
                                     unsigned long long b) {
    asm("fma.rn.f32x2 %0, %1, %2, %0;" : "+l"(d) : "l"(a), "l"(b));
}
__device__ __forceinline__ unsigned long long packdup(float x) {
    unsigned long long r;
    asm("mov.b64 %0, {%1, %1};" : "=l"(r) : "f"(x));
    return r;
}
__device__ __forceinline__ unsigned long long pack2(float a, float b) {
    unsigned long long r;
    asm("mov.b64 %0, {%1, %2};" : "=l"(r) : "f"(a), "f"(b));
    return r;
}
__device__ __forceinline__ float2 unpack2(unsigned long long v) {
    float2 r;
    asm("mov.b64 {%0, %1}, %2;" : "=f"(r.x), "=f"(r.y) : "l"(v));
    return r;
}

// ===========================================================================
// K1: heterogeneous — blocks [0,GB) compute P = feat @ W (f32 math, f16 P
// out); blocks [GB, GB+FB) bucket edges into g_slots.
// GEMM A stored as f32x2 ROW-PAIRS: sP[pair][k] = {A[2p][k], A[2p+1][k]}.
// One broadcast LDS.64 feeds 2 rows; fma2 against dup'd W scalar
// accumulates both rows at once -> 8 L1 wavefronts/k (was 12).
// ===========================================================================
__global__ void __launch_bounds__(256)
gemm_fill_kernel(const float* __restrict__ feat,
                 const float* __restrict__ W,
                 const int* __restrict__ src,
                 const int* __restrict__ dst,
                 const float* __restrict__ ew,
                 int E) {
    __shared__ unsigned long long sP[GEMM_ROWS / 2][D];   // 32KB pair-interleaved

    if (blockIdx.x >= GB) {
        // ---------------- fill part: one edge per thread ----------------
        int i = (blockIdx.x - GB) * 256 + threadIdx.x;
        if (i < E) {
            int d = __ldg(dst + i);
            int p = atomicAdd(&g_cursor[d], 1);
            if (p < CAP)
                g_slots[(size_t)d * CAP + p] =
                    make_int2(__ldg(src + i), __float_as_int(__ldg(ew + i)));
        }
        return;
    }

    // ------------- GEMM part: 64 rows = 32 pairs, 4 pairs per warp -------------
    const int t = threadIdx.x;
    const int block_row = blockIdx.x * GEMM_ROWS;

    // Staging: item (pair p, c4). Load the same float4 chunk from rows 2p and
    // 2p+1 (both coalesced), write 4 interleaved STS.64 pairs (conflict-free:
    // lane byte-stride 32, distinct banks per 128B phase).
    #pragma unroll
    for (int it = 0; it < (GEMM_ROWS / 2 * 32) / 256; it++) {
        int i  = it * 256 + t;
        int p  = i >> 5;
        int c4 = i & 31;
        int row0 = block_row + 2 * p;
        float4 f0 = (row0 < N_NODES)
            ? __ldg(reinterpret_cast<const float4*>(feat + (size_t)row0 * D) + c4)
            : make_float4(0.f, 0.f, 0.f, 0.f);
        float4 f1 = (row0 + 1 < N_NODES)
            ? __ldg(reinterpret_cast<const float4*>(feat + (size_t)(row0 + 1) * D) + c4)
            : make_float4(0.f, 0.f, 0.f, 0.f);
        sP[p][c4 * 4 + 0] = pack2(f0.x, f1.x);
        sP[p][c4 * 4 + 1] = pack2(f0.y, f1.y);
        sP[p][c4 * 4 + 2] = pack2(f0.z, f1.z);
        sP[p][c4 * 4 + 3] = pack2(f0.w, f1.w);
    }
    __syncthreads();

    const int warp = t >> 5;
    const int lane = t & 31;
    const int p0 = warp * 4;           // warp's first row-pair

    unsigned long long acc[4][4];      // [pair][col] = {even-row, odd-row}
    #pragma unroll
    for (int p = 0; p < 4; p++)
        #pragma unroll
        for (int c = 0; c < 4; c++) acc[p][c] = 0ull;

    const float4* W4 = reinterpret_cast<const float4*>(W);

    #pragma unroll 2
    for (int k = 0; k < D; k++) {
        float4 w = __ldg(W4 + k * (D / 4) + lane);   // cols [4l, 4l+4)
        unsigned long long w0 = packdup(w.x);
        unsigned long long w1 = packdup(w.y);
        unsigned long long w2 = packdup(w.z);
        unsigned long long w3 = packdup(w.w);
        #pragma unroll
        for (int p = 0; p < 4; p++) {
            unsigned long long a = sP[p0 + p][k];    // broadcast LDS.64
            fma2(acc[p][0], a, w0);
            fma2(acc[p][1], a, w1);
            fma2(acc[p][2], a, w2);
            fma2(acc[p][3], a, w3);
        }
    }

    // Epilogue: split pairs, convert to f16, one uint2 store per row.
    #pragma unroll
    for (int p = 0; p < 4; p++) {
        float2 c0 = unpack2(acc[p][0]);
        float2 c1 = unpack2(acc[p][1]);
        float2 c2 = unpack2(acc[p][2]);
        float2 c3 = unpack2(acc[p][3]);
        int row0 = block_row + 2 * (p0 + p);
        if (row0 < N_NODES) {
            __half2 h0 = __float22half2_rn(make_float2(c0.x, c1.x));
            __half2 h1 = __float22half2_rn(make_float2(c2.x, c3.x));
            uint2 pk;
            pk.x = *reinterpret_cast<const unsigned int*>(&h0);
            pk.y = *reinterpret_cast<const unsigned int*>(&h1);
            g_Ph[(size_t)row0 * 32 + lane] = pk;
        }
        if (row0 + 1 < N_NODES) {
            __half2 h0 = __float22half2_rn(make_float2(c0.y, c1.y));
            __half2 h1 = __float22half2_rn(make_float2(c2.y, c3.y));
            uint2 pk;
            pk.x = *reinterpret_cast<const unsigned int*>(&h0);
            pk.y = *reinterpret_cast<const unsigned int*>(&h1);
            g_Ph[(size_t)(row0 + 1) * 32 + lane] = pk;
        }
    }
}

// ===========================================================================
// K2: gather.  out[n] = 0.5*(P[n] + sum w*P[src]), P in f16, fp32 accum.
// One warp per node; 8-wide MLP; shfl-served slot entries.
// (Unchanged from the proven R10/R12 version.)
// ===========================================================================
__global__ void __launch_bounds__(256)
gather_kernel(float* __restrict__ out) {
    int gid  = blockIdx.x * blockDim.x + threadIdx.x;
    int node = gid >> 5;
    int lane = gid & 31;
    if (node >= N_NODES) return;

    int cnt = g_cursor[node];
    if (cnt > CAP) cnt = CAP;
    const int2* sl = g_slots + (size_t)node * CAP;

    int2 my = make_int2(0, 0);
    if (lane < cnt) my = __ldg(sl + lane);

    // self term
    float4 acc;
    {
        uint2 pk = g_Ph[(size_t)node * 32 + lane];
        float2 f0 = __half22float2(*reinterpret_cast<const __half2*>(&pk.x));
        float2 f1 = __half22float2(*reinterpret_cast<const __half2*>(&pk.y));
        acc = make_float4(f0.x, f0.y, f1.x, f1.y);
    }

    const int lim = (cnt < 32) ? cnt : 32;
    int i = 0;
    for (; i + 8 <= lim; i += 8) {
        int   s[8];
        float w[8];
        #pragma unroll
        for (int j = 0; j < 8; j++) {
            s[j] = __shfl_sync(0xFFFFFFFFu, my.x, i + j);
            w[j] = __int_as_float(__shfl_sync(0xFFFFFFFFu, my.y, i + j));
        }
        uint2 pv[8];
        #pragma unroll
        for (int j = 0; j < 8; j++) pv[j] = g_Ph[(size_t)s[j] * 32 + lane];
        #pragma unroll
        for (int j = 0; j < 8; j++) {
            float2 f0 = __half22float2(*reinterpret_cast<const __half2*>(&pv[j].x));
            float2 f1 = __half22float2(*reinterpret_cast<const __half2*>(&pv[j].y));
            acc.x += w[j] * f0.x;
            acc.y += w[j] * f0.y;
            acc.z += w[j] * f1.x;
            acc.w += w[j] * f1.y;
        }
    }
    for (; i < lim; i++) {
        int   s = __shfl_sync(0xFFFFFFFFu, my.x, i);
        float w = __int_as_float(__shfl_sync(0xFFFFFFFFu, my.y, i));
        uint2 pk = g_Ph[(size_t)s * 32 + lane];
        float2 f0 = __half22float2(*reinterpret_cast<const __half2*>(&pk.x));
        float2 f1 = __half22float2(*reinterpret_cast<const __half2*>(&pk.y));
        acc.x += w * f0.x; acc.y += w * f0.y;
        acc.z += w * f1.x; acc.w += w * f1.y;
    }
    for (; i < cnt; i++) {   // rare tail: degree > 32
        int2 e = __ldg(sl + i);
        float w = __int_as_float(e.y);
        uint2 pk = g_Ph[(size_t)e.x * 32 + lane];
        float2 f0 = __half22float2(*reinterpret_cast<const __half2*>(&pk.x));
        float2 f1 = __half22float2(*reinterpret_cast<const __half2*>(&pk.y));
        acc.x += w * f0.x; acc.y += w * f0.y;
        acc.z += w * f1.x; acc.w += w * f1.y;
    }

    acc.x *= 0.5f; acc.y *= 0.5f; acc.z *= 0.5f; acc.w *= 0.5f;
    reinterpret_cast<float4*>(out)[(size_t)node * 32 + lane] = acc;

    if (lane == 0) g_cursor[node] = 0;   // restore invariant for next call
}

// ===========================================================================
// Launch. Inputs: feature [N*D] f32, edge_src [E] i32, edge_dst [E] i32,
// edge_w [E] f32, weight [D*D] f32. Output: [N*D] f32.
// ===========================================================================
extern "C" void kernel_launch(void* const* d_in, const int* in_sizes, int n_in,
                              void* d_out, int out_size) {
    const float* feat = (const float*)d_in[0];
    const int*   src  = (const int*)d_in[1];
    const int*   dst  = (const int*)d_in[2];
    const float* ew   = (const float*)d_in[3];
    const float* W    = (const float*)d_in[4];
    float* out = (float*)d_out;

    const int E  = in_sizes[1];
    const int FB = (E + 255) / 256;

    gemm_fill_kernel<<<GB + FB, 256>>>(feat, W, src, dst, ew, E);
    gather_kernel<<<(N_NODES * 32 + 255) / 256, 256>>>(out);
}